// round 15
// baseline (speedup 1.0000x reference)
#include <cuda_runtime.h>
#include <cuda_fp16.h>
#include <cstdint>

#define NB 8
#define TDIM 4096
#define SDIM 512
#define CDIM 1024
#define NCHUNK 16
#define NRCH 512
#define NEG_INF (-3.0e38f)

typedef __half hf;

// ---------------- scratch (static device globals; no allocation) ----------------
__device__ float g_sc [(size_t)NB * TDIM * SDIM];
__device__ float g_vsc[(size_t)NB * SDIM * TDIM];
__device__ __align__(16) hf g_Xh [(size_t)NB * TDIM * CDIM], g_Xl [(size_t)NB * TDIM * CDIM];
__device__ __align__(16) hf g_XTh[(size_t)NB * CDIM * TDIM];
__device__ __align__(16) hf g_Kh [(size_t)NB * SDIM * CDIM];
__device__ __align__(16) hf g_Vh [(size_t)NB * SDIM * CDIM], g_Vl [(size_t)NB * SDIM * CDIM];
__device__ __align__(16) hf g_VTh[(size_t)NB * CDIM * SDIM];
__device__ __align__(16) hf g_Ph [(size_t)NB * TDIM * SDIM];
__device__ __align__(16) hf g_P2h[(size_t)NB * SDIM * TDIM];
__device__ __align__(16) hf g_P3h[(size_t)NB * SDIM * TDIM];
__device__ float g_pmL[(size_t)NB * NRCH * SDIM], g_psL[(size_t)NB * NRCH * SDIM];
__device__ float g_pcm[NB * NCHUNK * SDIM], g_pcs[NB * NCHUNK * SDIM];
__device__ float g_cm [NB * SDIM], g_cs [NB * SDIM];
__device__ float g_rm [NB * TDIM], g_rs [NB * TDIM];

// ---------------- PTX helpers ----------------
__device__ __forceinline__ void cp16(uint32_t dst, const void* src) {
    asm volatile("cp.async.cg.shared.global [%0], [%1], 16;" :: "r"(dst), "l"(src));
}
__device__ __forceinline__ void cp_commit() {
    asm volatile("cp.async.commit_group;" ::: "memory");
}
template <int N>
__device__ __forceinline__ void cp_wait() {
    asm volatile("cp.async.wait_group %0;" :: "n"(N) : "memory");
}
__device__ __forceinline__ void ldsm4(uint32_t* r, uint32_t addr) {
    asm volatile("ldmatrix.sync.aligned.m8n8.x4.shared.b16 {%0,%1,%2,%3}, [%4];"
                 : "=r"(r[0]), "=r"(r[1]), "=r"(r[2]), "=r"(r[3]) : "r"(addr));
}
__device__ __forceinline__ void mma16816(float* d, const uint32_t* a, const uint32_t* b) {
    asm volatile(
        "mma.sync.aligned.m16n8k16.row.col.f32.f16.f16.f32 "
        "{%0,%1,%2,%3}, {%4,%5,%6,%7}, {%8,%9}, {%0,%1,%2,%3};"
        : "+f"(d[0]), "+f"(d[1]), "+f"(d[2]), "+f"(d[3])
        : "r"(a[0]), "r"(a[1]), "r"(a[2]), "r"(a[3]), "r"(b[0]), "r"(b[1]));
}
__device__ __forceinline__ void split1(float f, hf& h, hf& l) {
    h = __float2half_rn(f);
    l = __float2half_rn(f - __half2float(h));
}

// ---------------------------------------------------------------------------
// Shared GEMM body. Tile 128x128, BK=64, 256 thr, warp tile 64x32.
// PASSES=2: stage = {Ah,Al,Bh} 48KB x2 stages.  PASSES=1: {Ah,Bh} 32KB x3.
// Runtime residual pointer (nullptr = none).
// ---------------------------------------------------------------------------
template <int PASSES>
__device__ __forceinline__ void gemm_body(
    const hf* __restrict__ pAh, const hf* __restrict__ pAl,
    const hf* __restrict__ pBh, const float* __restrict__ Rp,
    float* __restrict__ Co, float scale, int K, int Nglob,
    int m0, int n0, char* dsm)
{
    constexpr int NST  = (PASSES == 1) ? 3 : 2;
    constexpr int STG  = (PASSES == 1) ? 32768 : 49152;
    constexpr int BOFC = (PASSES == 1) ? 16384 : 32768;
    constexpr int NCH  = (PASSES == 1) ? 8 : 12;

    const uint32_t sbase = (uint32_t)__cvta_generic_to_shared(dsm);
    const int tid = threadIdx.x, wid = tid >> 5, lane = tid & 31;
    const int wm = wid & 1, wn = wid >> 1;
    const int KT = K >> 6;

    auto load = [&](int kc, int s) {
        uint32_t st = sbase + s * STG;
#pragma unroll
        for (int t = 0; t < NCH; t++) {
            int idx = t * 256 + tid;
            int tile = idx >> 10;
            int ch = idx & 1023;
            int row = ch >> 3, c = ch & 7;
            const hf* src;
            int rbase;
            if (PASSES == 2) {
                src = (tile == 0) ? pAh : (tile == 1 ? pAl : pBh);
                rbase = (tile < 2) ? m0 : n0;
            } else {
                src = (tile == 0) ? pAh : pBh;
                rbase = (tile == 0) ? m0 : n0;
            }
            size_t goff = (size_t)(rbase + row) * K + kc * 64 + c * 8;
            uint32_t dst = st + (uint32_t)(tile * 16384 + row * 128 + ((c ^ (row & 7)) * 16));
            cp16(dst, (const char*)src + goff * 2);
        }
        cp_commit();
    };

    float acc[4][4][4];
#pragma unroll
    for (int mi = 0; mi < 4; mi++)
#pragma unroll
        for (int ni = 0; ni < 4; ni++)
#pragma unroll
            for (int j = 0; j < 4; j++) acc[mi][ni][j] = 0.f;

    const int rowa = wm * 64 + (lane & 15);
    const int ka   = lane >> 4;
    const int xa   = rowa & 7;
    const int rowb = wn * 32 + (lane & 7) + ((lane >> 4) << 3);
    const int kb   = (lane >> 3) & 1;
    const int xb   = rowb & 7;

    auto compute = [&](int s) {
        uint32_t st = sbase + s * STG;
#pragma unroll
        for (int ks = 0; ks < 4; ks++) {
            uint32_t ah[4][4], al[4][4], bh[2][4];
#pragma unroll
            for (int mi = 0; mi < 4; mi++) {
                uint32_t rb = st + (uint32_t)((rowa + mi * 16) * 128);
                uint32_t co = (uint32_t)(((2 * ks + ka) ^ xa) * 16);
                ldsm4(ah[mi], rb + co);
                if (PASSES == 2)
                    ldsm4(al[mi], rb + 16384 + co);
            }
#pragma unroll
            for (int j = 0; j < 2; j++) {
                uint32_t rb = st + BOFC + (uint32_t)((rowb + j * 16) * 128);
                ldsm4(bh[j], rb + (uint32_t)(((2 * ks + kb) ^ xb) * 16));
            }
#pragma unroll
            for (int mi = 0; mi < 4; mi++)
#pragma unroll
                for (int j = 0; j < 2; j++) {
                    mma16816(acc[mi][2 * j],     ah[mi], bh[j]);
                    mma16816(acc[mi][2 * j + 1], ah[mi], bh[j] + 2);
                }
            if (PASSES == 2) {
#pragma unroll
                for (int mi = 0; mi < 4; mi++)
#pragma unroll
                    for (int j = 0; j < 2; j++) {
                        mma16816(acc[mi][2 * j],     al[mi], bh[j]);
                        mma16816(acc[mi][2 * j + 1], al[mi], bh[j] + 2);
                    }
            }
        }
    };

#pragma unroll
    for (int i = 0; i < NST - 1; i++)
        if (i < KT) load(i, i);

    for (int ci = 0; ci < KT; ci++) {
        if (ci < KT - (NST - 1)) cp_wait<NST - 2>(); else cp_wait<0>();
        __syncthreads();
        if (ci + NST - 1 < KT) load(ci + NST - 1, (ci + NST - 1) % NST);
        compute(ci % NST);
    }

    const int rbase = m0 + wm * 64 + (lane >> 2);
    const int cbase = n0 + wn * 32 + (lane & 3) * 2;
#pragma unroll
    for (int mi = 0; mi < 4; mi++) {
#pragma unroll
        for (int ni = 0; ni < 4; ni++) {
#pragma unroll
            for (int h = 0; h < 2; h++) {
                int r = rbase + mi * 16 + h * 8;
                int c = cbase + ni * 8;
                float2 v;
                v.x = acc[mi][ni][2 * h]     * scale;
                v.y = acc[mi][ni][2 * h + 1] * scale;
                size_t go = (size_t)r * Nglob + c;
                if (Rp) {
                    float2 d = *(const float2*)(Rp + go);
                    v.x += d.x; v.y += d.y;
                }
                *(float2*)(Co + go) = v;
            }
        }
    }
}

// Merged scores + v_scores (both 2-pass, K=CDIM). grid = (128, 1, 2*NB).
__global__ void __launch_bounds__(256, 2)
gemm_dual(const hf* __restrict__ Xh, const hf* __restrict__ Xl,
          const hf* __restrict__ Kh, const hf* __restrict__ Vh,
          const hf* __restrict__ Vl, float* __restrict__ sc,
          float* __restrict__ vsc, float scale)
{
    extern __shared__ char dsm[];
    int which = blockIdx.z >= NB;
    int b = blockIdx.z & (NB - 1);
    if (!which) {
        // scores[T,S]: A = X (hi/lo), B = K(hi); tiles_x = SDIM/128 = 4
        int m0 = (blockIdx.x >> 2) * 128, n0 = (blockIdx.x & 3) * 128;
        gemm_body<2>(Xh + (size_t)b * TDIM * CDIM, Xl + (size_t)b * TDIM * CDIM,
                     Kh + (size_t)b * SDIM * CDIM, nullptr,
                     sc + (size_t)b * TDIM * SDIM, scale, CDIM, SDIM, m0, n0, dsm);
    } else {
        // v_scores[S,T]: A = V (hi/lo), B = X(hi); tiles_x = TDIM/128 = 32
        int m0 = (blockIdx.x >> 5) * 128, n0 = (blockIdx.x & 31) * 128;
        gemm_body<2>(Vh + (size_t)b * SDIM * CDIM, Vl + (size_t)b * SDIM * CDIM,
                     Xh + (size_t)b * TDIM * CDIM, nullptr,
                     vsc + (size_t)b * SDIM * TDIM, scale, CDIM, TDIM, m0, n0, dsm);
    }
}

// Merged k_t + v_t + att (all 1-pass). Long K=4096 tiles first.
// grid.x = 256 (k_t) + 256 (v_t) + 2048 (att) = 2560.
__global__ void __launch_bounds__(256, 2)
gemm_tri(const hf* __restrict__ Ph, const hf* __restrict__ P2h,
         const hf* __restrict__ P3h, const hf* __restrict__ VTh,
         const hf* __restrict__ XTh, const float* __restrict__ kin,
         const float* __restrict__ vin, float* __restrict__ att,
         float* __restrict__ ktv, float* __restrict__ vtv)
{
    extern __shared__ char dsm[];
    int g = blockIdx.x;
    if (g < 512) {
        // k_t (g<256) / v_t: [S,C] = P{2,3}[S,T] * XT[C,T] + residual; 32 tiles/batch
        int isv = g >= 256;
        int r = g & 255;
        int b = r >> 5, t = r & 31;
        int m0 = (t >> 3) * 128, n0 = (t & 7) * 128;
        const hf* A = (isv ? P3h : P2h) + (size_t)b * SDIM * TDIM;
        const float* R = (isv ? vin : kin) + (size_t)b * SDIM * CDIM;
        float* C = (isv ? vtv : ktv) + (size_t)b * SDIM * CDIM;
        gemm_body<1>(A, nullptr, XTh + (size_t)b * CDIM * TDIM, R, C,
                     1.0f, TDIM, CDIM, m0, n0, dsm);
    } else {
        // att: [T,C] = P[T,S] * VT[C,S]; 256 tiles/batch
        int r = g - 512;
        int b = r >> 8, t = r & 255;
        int m0 = (t >> 3) * 128, n0 = (t & 7) * 128;
        gemm_body<1>(Ph + (size_t)b * TDIM * SDIM, nullptr,
                     VTh + (size_t)b * CDIM * SDIM, nullptr,
                     att + (size_t)b * TDIM * CDIM, 1.0f, SDIM, CDIM, m0, n0, dsm);
    }
}

// ---------------- conversion kernels ----------------
__global__ void stx_k(const float* __restrict__ in, hf* __restrict__ oh,
                      hf* __restrict__ ol, hf* __restrict__ ohT, int R, int Cc)
{
    __shared__ float t[32][33];
    int b = blockIdx.z;
    int c0 = blockIdx.x * 32, r0 = blockIdx.y * 32;
    const float* ip = in + (size_t)b * R * Cc;
    size_t nb = (size_t)b * R * Cc;
    int tx = threadIdx.x, ty = threadIdx.y;
#pragma unroll
    for (int i = 0; i < 4; i++) {
        int r = r0 + ty + i * 8;
        float v = ip[(size_t)r * Cc + c0 + tx];
        t[ty + i * 8][tx] = v;
        hf h, l;
        split1(v, h, l);
        oh[nb + (size_t)r * Cc + c0 + tx] = h;
        if (ol) ol[nb + (size_t)r * Cc + c0 + tx] = l;
    }
    __syncthreads();
#pragma unroll
    for (int i = 0; i < 4; i++) {
        int c = c0 + ty + i * 8;
        ohT[nb + (size_t)c * R + r0 + tx] = __float2half_rn(t[tx][ty + i * 8]);
    }
}

__global__ void splith_k(const float* __restrict__ in, hf* __restrict__ h, size_t n4)
{
    size_t i = (size_t)blockIdx.x * blockDim.x + threadIdx.x;
    if (i >= n4) return;
    float4 v = ((const float4*)in)[i];
    __half2* hp = (__half2*)h;
    hp[i * 2]     = __halves2half2(__float2half_rn(v.x), __float2half_rn(v.y));
    hp[i * 2 + 1] = __halves2half2(__float2half_rn(v.z), __float2half_rn(v.w));
}

// FUSED row softmax over 512 + per-8-row column partials (one sc read)
__global__ void softfuse512_k(const float* __restrict__ S, hf* __restrict__ oh,
                              float* __restrict__ rmg, float* __restrict__ rsg,
                              float* __restrict__ pm, float* __restrict__ ps)
{
    __shared__ float sv[SDIM * 9];
    int warp = threadIdx.x >> 5, lane = threadIdx.x & 31;
    int b = blockIdx.y, rb = blockIdx.x;
    size_t row = (size_t)b * TDIM + rb * 8 + warp;
    const float4* p4 = (const float4*)(S + row * SDIM);
    float4 v[4];
    float m = NEG_INF;
#pragma unroll
    for (int i = 0; i < 4; i++) {
        v[i] = p4[lane + i * 32];
        m = fmaxf(m, fmaxf(fmaxf(v[i].x, v[i].y), fmaxf(v[i].z, v[i].w)));
        int c0 = 4 * (lane + i * 32);
        sv[(c0 + 0) * 9 + warp] = v[i].x;
        sv[(c0 + 1) * 9 + warp] = v[i].y;
        sv[(c0 + 2) * 9 + warp] = v[i].z;
        sv[(c0 + 3) * 9 + warp] = v[i].w;
    }
#pragma unroll
    for (int o = 16; o > 0; o >>= 1) m = fmaxf(m, __shfl_xor_sync(0xffffffffu, m, o));
    float s = 0.f;
#pragma unroll
    for (int i = 0; i < 4; i++)
        s += __expf(v[i].x - m) + __expf(v[i].y - m) + __expf(v[i].z - m) + __expf(v[i].w - m);
#pragma unroll
    for (int o = 16; o > 0; o >>= 1) s += __shfl_xor_sync(0xffffffffu, s, o);
    if (!lane) { rmg[row] = m; rsg[row] = s; }
    float inv = __fdividef(1.0f, s);
    __half2* hp = (__half2*)(oh + row * SDIM);
#pragma unroll
    for (int i = 0; i < 4; i++) {
        int p = (lane + i * 32) * 2;
        hp[p]     = __halves2half2(__float2half_rn(__expf(v[i].x - m) * inv),
                                   __float2half_rn(__expf(v[i].y - m) * inv));
        hp[p + 1] = __halves2half2(__float2half_rn(__expf(v[i].z - m) * inv),
                                   __float2half_rn(__expf(v[i].w - m) * inv));
    }
    __syncthreads();
#pragma unroll
    for (int h = 0; h < 2; h++) {
        int sc_ = threadIdx.x + h * 256;
        float cmx = NEG_INF;
#pragma unroll
        for (int w = 0; w < 8; w++) cmx = fmaxf(cmx, sv[sc_ * 9 + w]);
        float csum = 0.f;
#pragma unroll
        for (int w = 0; w < 8; w++) csum += __expf(sv[sc_ * 9 + w] - cmx);
        size_t o = ((size_t)b * NRCH + rb) * SDIM + sc_;
        pm[o] = cmx; ps[o] = csum;
    }
}

__global__ void colcomb1_k(const float* __restrict__ pm, const float* __restrict__ ps,
                           float* __restrict__ pm2, float* __restrict__ ps2)
{
    int b = blockIdx.y, g = blockIdx.x, s = threadIdx.x;
    float m = NEG_INF, sum = 0.f;
    for (int c = 0; c < NRCH / NCHUNK; c++) {
        size_t idx = ((size_t)b * NRCH + g * (NRCH / NCHUNK) + c) * SDIM + s;
        float mm = pm[idx];
        float nm = fmaxf(m, mm);
        sum = sum * __expf(m - nm) + ps[idx] * __expf(mm - nm);
        m = nm;
    }
    pm2[(b * NCHUNK + g) * SDIM + s] = m;
    ps2[(b * NCHUNK + g) * SDIM + s] = sum;
}

__global__ void colcomb_k(const float* __restrict__ pm, const float* __restrict__ ps,
                          float* __restrict__ cm, float* __restrict__ cs)
{
    int b = blockIdx.x, s = threadIdx.x;
    float m = NEG_INF;
#pragma unroll
    for (int c = 0; c < NCHUNK; c++) m = fmaxf(m, pm[(b * NCHUNK + c) * SDIM + s]);
    float sum = 0.f;
#pragma unroll
    for (int c = 0; c < NCHUNK; c++)
        sum += ps[(b * NCHUNK + c) * SDIM + s] * __expf(pm[(b * NCHUNK + c) * SDIM + s] - m);
    cm[b * SDIM + s] = m;
    cs[b * SDIM + s] = sum;
}

// col softmax + transpose from Ph
__global__ void pcolT_k(const hf* __restrict__ Ph, const float* __restrict__ rmg,
                        const float* __restrict__ rsg, const float* __restrict__ cm,
                        const float* __restrict__ cs, hf* __restrict__ oh)
{
    __shared__ float t[32][33];
    int b = blockIdx.z;
    int s0 = blockIdx.x * 32, t0 = blockIdx.y * 32;
    const hf* ip = Ph + (size_t)b * TDIM * SDIM;
    int tx = threadIdx.x, ty = threadIdx.y;
#pragma unroll
    for (int i = 0; i < 4; i++) {
        int tr = t0 + ty + i * 8;
        t[ty + i * 8][tx] = __half2float(ip[(size_t)tr * SDIM + s0 + tx]);
    }
    __syncthreads();
    size_t ob = (size_t)b * SDIM * TDIM;
#pragma unroll
    for (int i = 0; i < 4; i++) {
        int s = s0 + ty + i * 8;
        int tcol = t0 + tx;
        float cminv = __fdividef(1.0f, cs[b * SDIM + s]);
        float cmv = cm[b * SDIM + s];
        float f = rsg[b * TDIM + tcol] * __expf(rmg[b * TDIM + tcol] - cmv) * cminv;
        oh[ob + (size_t)s * TDIM + t0 + tx] = __float2half_rn(t[tx][ty + i * 8] * f);
    }
}

// row softmax over 4096 -> fp16 hi only
__global__ void softrow4096_k(const float* __restrict__ S, hf* __restrict__ oh)
{
    __shared__ float sh[16];
    int tid = threadIdx.x, lane = tid & 31, warp = tid >> 5;
    size_t row = blockIdx.x;
    const float4* p4 = (const float4*)(S + row * TDIM);
    float4 v[2];
    float m = NEG_INF;
#pragma unroll
    for (int i = 0; i < 2; i++) {
        v[i] = p4[tid + i * 512];
        m = fmaxf(m, fmaxf(fmaxf(v[i].x, v[i].y), fmaxf(v[i].z, v[i].w)));
    }
#pragma unroll
    for (int o = 16; o > 0; o >>= 1) m = fmaxf(m, __shfl_xor_sync(0xffffffffu, m, o));
    if (!lane) sh[warp] = m;
    __syncthreads();
    if (tid < 16) {
        float t = sh[tid];
#pragma unroll
        for (int o = 8; o > 0; o >>= 1) t = fmaxf(t, __shfl_xor_sync(0xffffu, t, o));
        if (!tid) sh[0] = t;
    }
    __syncthreads();
    m = sh[0];
    __syncthreads();
    float s = 0.f;
#pragma unroll
    for (int i = 0; i < 2; i++)
        s += __expf(v[i].x - m) + __expf(v[i].y - m) + __expf(v[i].z - m) + __expf(v[i].w - m);
#pragma unroll
    for (int o = 16; o > 0; o >>= 1) s += __shfl_xor_sync(0xffffffffu, s, o);
    if (!lane) sh[warp] = s;
    __syncthreads();
    if (tid < 16) {
        float t = sh[tid];
#pragma unroll
        for (int o = 8; o > 0; o >>= 1) t += __shfl_xor_sync(0xffffu, t, o);
        if (!tid) sh[0] = t;
    }
    __syncthreads();
    float inv = __fdividef(1.0f, sh[0]);
    __half2* hp = (__half2*)(oh + row * TDIM);
#pragma unroll
    for (int i = 0; i < 2; i++) {
        int p = (tid + i * 512) * 2;
        hp[p]     = __halves2half2(__float2half_rn(__expf(v[i].x - m) * inv),
                                   __float2half_rn(__expf(v[i].y - m) * inv));
        hp[p + 1] = __halves2half2(__float2half_rn(__expf(v[i].z - m) * inv),
                                   __float2half_rn(__expf(v[i].w - m) * inv));
    }
}

// ---------------- launch ----------------
extern "C" void kernel_launch(void* const* d_in, const int* in_sizes, int n_in,
                              void* d_out, int out_size)
{
    const float* x   = (const float*)d_in[0];
    const float* kin = (const float*)d_in[1];
    const float* vin = (const float*)d_in[2];

    float* att = (float*)d_out;
    float* ktv = att + (size_t)NB * TDIM * CDIM;
    float* vtv = ktv + (size_t)NB * SDIM * CDIM;

    float *sc, *vsc, *pmL, *psL, *pcm, *pcs, *cm, *cs, *rm, *rs;
    hf *Xh, *Xl, *XTh, *Kh, *Vh, *Vl, *VTh;
    hf *Ph, *P2h, *P3h;
    cudaGetSymbolAddress((void**)&sc, g_sc);     cudaGetSymbolAddress((void**)&vsc, g_vsc);
    cudaGetSymbolAddress((void**)&pmL, g_pmL);   cudaGetSymbolAddress((void**)&psL, g_psL);
    cudaGetSymbolAddress((void**)&pcm, g_pcm);   cudaGetSymbolAddress((void**)&pcs, g_pcs);
    cudaGetSymbolAddress((void**)&cm, g_cm);     cudaGetSymbolAddress((void**)&cs, g_cs);
    cudaGetSymbolAddress((void**)&rm, g_rm);     cudaGetSymbolAddress((void**)&rs, g_rs);
    cudaGetSymbolAddress((void**)&Xh, g_Xh);     cudaGetSymbolAddress((void**)&Xl, g_Xl);
    cudaGetSymbolAddress((void**)&XTh, g_XTh);
    cudaGetSymbolAddress((void**)&Kh, g_Kh);
    cudaGetSymbolAddress((void**)&Vh, g_Vh);     cudaGetSymbolAddress((void**)&Vl, g_Vl);
    cudaGetSymbolAddress((void**)&VTh, g_VTh);
    cudaGetSymbolAddress((void**)&Ph, g_Ph);
    cudaGetSymbolAddress((void**)&P2h, g_P2h);
    cudaGetSymbolAddress((void**)&P3h, g_P3h);

    const int SMEM = 98304;
    cudaFuncSetAttribute(gemm_dual, cudaFuncAttributeMaxDynamicSharedMemorySize, SMEM);
    cudaFuncSetAttribute(gemm_tri,  cudaFuncAttributeMaxDynamicSharedMemorySize, SMEM);

    const float scale = 0.03125f;  // 1/sqrt(1024)

    // operand prep
    stx_k<<<dim3(CDIM / 32, TDIM / 32, NB), dim3(32, 8)>>>(x, Xh, Xl, XTh, TDIM, CDIM);
    {
        size_t n4 = (size_t)NB * SDIM * CDIM / 4;
        splith_k<<<(unsigned)((n4 + 255) / 256), 256>>>(kin, Kh, n4);
    }
    stx_k<<<dim3(CDIM / 32, SDIM / 32, NB), dim3(32, 8)>>>(vin, Vh, Vl, VTh, SDIM, CDIM);

    // merged scores + v_scores (2-pass, K=1024), 2048 CTAs
    gemm_dual<<<dim3(128, 1, 2 * NB), 256, SMEM>>>(Xh, Xl, Kh, Vh, Vl, sc, vsc, scale);

    // aux chain
    softfuse512_k<<<dim3(NRCH, NB), 256>>>(sc, Ph, rm, rs, pmL, psL);
    colcomb1_k<<<dim3(NCHUNK, NB), SDIM>>>(pmL, psL, pcm, pcs);
    colcomb_k<<<NB, SDIM>>>(pcm, pcs, cm, cs);
    pcolT_k<<<dim3(SDIM / 32, TDIM / 32, NB), dim3(32, 8)>>>(Ph, rm, rs, cm, cs, P2h);
    softrow4096_k<<<NB * SDIM, 512>>>(vsc, P3h);

    // merged k_t + v_t + att (1-pass), long tiles first, 2560 CTAs
    gemm_tri<<<2560, 256, SMEM>>>(Ph, P2h, P3h, VTh, XTh, kin, vin, att, ktv, vtv);
}

// round 16
// speedup vs baseline: 1.5167x; 1.5167x over previous
#include <cuda_runtime.h>
#include <cuda_fp16.h>
#include <cstdint>

#define NB 8
#define TDIM 4096
#define SDIM 512
#define CDIM 1024
#define NCHUNK 16
#define NRCH 512
#define NEG_INF (-3.0e38f)

typedef __half hf;

// ---------------- scratch (static device globals; no allocation) ----------------
__device__ float g_sc [(size_t)NB * TDIM * SDIM];
__device__ float g_vsc[(size_t)NB * SDIM * TDIM];
__device__ __align__(16) hf g_Xh [(size_t)NB * TDIM * CDIM], g_Xl [(size_t)NB * TDIM * CDIM];
__device__ __align__(16) hf g_XTh[(size_t)NB * CDIM * TDIM];
__device__ __align__(16) hf g_Kh [(size_t)NB * SDIM * CDIM];
__device__ __align__(16) hf g_Vh [(size_t)NB * SDIM * CDIM], g_Vl [(size_t)NB * SDIM * CDIM];
__device__ __align__(16) hf g_VTh[(size_t)NB * CDIM * SDIM];
__device__ __align__(16) hf g_Ph [(size_t)NB * TDIM * SDIM];
__device__ __align__(16) hf g_P2h[(size_t)NB * SDIM * TDIM];
__device__ __align__(16) hf g_P3h[(size_t)NB * SDIM * TDIM];
__device__ float g_pmL[(size_t)NB * NRCH * SDIM], g_psL[(size_t)NB * NRCH * SDIM];
__device__ float g_pcm[NB * NCHUNK * SDIM], g_pcs[NB * NCHUNK * SDIM];
__device__ float g_cm [NB * SDIM], g_cs [NB * SDIM];
__device__ float g_rm [NB * TDIM], g_rs [NB * TDIM];

// ---------------- PTX helpers ----------------
__device__ __forceinline__ void cp16(uint32_t dst, const void* src) {
    asm volatile("cp.async.cg.shared.global [%0], [%1], 16;" :: "r"(dst), "l"(src));
}
__device__ __forceinline__ void cp_commit() {
    asm volatile("cp.async.commit_group;" ::: "memory");
}
template <int N>
__device__ __forceinline__ void cp_wait() {
    asm volatile("cp.async.wait_group %0;" :: "n"(N) : "memory");
}
__device__ __forceinline__ void ldsm4(uint32_t* r, uint32_t addr) {
    asm volatile("ldmatrix.sync.aligned.m8n8.x4.shared.b16 {%0,%1,%2,%3}, [%4];"
                 : "=r"(r[0]), "=r"(r[1]), "=r"(r[2]), "=r"(r[3]) : "r"(addr));
}
__device__ __forceinline__ void mma16816(float* d, const uint32_t* a, const uint32_t* b) {
    asm volatile(
        "mma.sync.aligned.m16n8k16.row.col.f32.f16.f16.f32 "
        "{%0,%1,%2,%3}, {%4,%5,%6,%7}, {%8,%9}, {%0,%1,%2,%3};"
        : "+f"(d[0]), "+f"(d[1]), "+f"(d[2]), "+f"(d[3])
        : "r"(a[0]), "r"(a[1]), "r"(a[2]), "r"(a[3]), "r"(b[0]), "r"(b[1]));
}
__device__ __forceinline__ void split1(float f, hf& h, hf& l) {
    h = __float2half_rn(f);
    l = __float2half_rn(f - __half2float(h));
}

// ---------------------------------------------------------------------------
// Shared GEMM body. Tile 128x128, BK=64, 256 thr, warp tile 64x32.
// PASSES=2: stage = {Ah,Al,Bh} 48KB x2 stages.  PASSES=1: {Ah,Bh} 32KB x3.
// Runtime residual pointer (nullptr = none).
// ---------------------------------------------------------------------------
template <int PASSES>
__device__ __forceinline__ void gemm_body(
    const hf* __restrict__ pAh, const hf* __restrict__ pAl,
    const hf* __restrict__ pBh, const float* __restrict__ Rp,
    float* __restrict__ Co, float scale, int K, int Nglob,
    int m0, int n0, char* dsm)
{
    constexpr int NST  = (PASSES == 1) ? 3 : 2;
    constexpr int STG  = (PASSES == 1) ? 32768 : 49152;
    constexpr int BOFC = (PASSES == 1) ? 16384 : 32768;
    constexpr int NCH  = (PASSES == 1) ? 8 : 12;

    const uint32_t sbase = (uint32_t)__cvta_generic_to_shared(dsm);
    const int tid = threadIdx.x, wid = tid >> 5, lane = tid & 31;
    const int wm = wid & 1, wn = wid >> 1;
    const int KT = K >> 6;

    auto load = [&](int kc, int s) {
        uint32_t st = sbase + s * STG;
#pragma unroll
        for (int t = 0; t < NCH; t++) {
            int idx = t * 256 + tid;
            int tile = idx >> 10;
            int ch = idx & 1023;
            int row = ch >> 3, c = ch & 7;
            const hf* src;
            int rbase;
            if (PASSES == 2) {
                src = (tile == 0) ? pAh : (tile == 1 ? pAl : pBh);
                rbase = (tile < 2) ? m0 : n0;
            } else {
                src = (tile == 0) ? pAh : pBh;
                rbase = (tile == 0) ? m0 : n0;
            }
            size_t goff = (size_t)(rbase + row) * K + kc * 64 + c * 8;
            uint32_t dst = st + (uint32_t)(tile * 16384 + row * 128 + ((c ^ (row & 7)) * 16));
            cp16(dst, (const char*)src + goff * 2);
        }
        cp_commit();
    };

    float acc[4][4][4];
#pragma unroll
    for (int mi = 0; mi < 4; mi++)
#pragma unroll
        for (int ni = 0; ni < 4; ni++)
#pragma unroll
            for (int j = 0; j < 4; j++) acc[mi][ni][j] = 0.f;

    const int rowa = wm * 64 + (lane & 15);
    const int ka   = lane >> 4;
    const int xa   = rowa & 7;
    const int rowb = wn * 32 + (lane & 7) + ((lane >> 4) << 3);
    const int kb   = (lane >> 3) & 1;
    const int xb   = rowb & 7;

    auto compute = [&](int s) {
        uint32_t st = sbase + s * STG;
#pragma unroll
        for (int ks = 0; ks < 4; ks++) {
            uint32_t ah[4][4], al[4][4], bh[2][4];
#pragma unroll
            for (int mi = 0; mi < 4; mi++) {
                uint32_t rb = st + (uint32_t)((rowa + mi * 16) * 128);
                uint32_t co = (uint32_t)(((2 * ks + ka) ^ xa) * 16);
                ldsm4(ah[mi], rb + co);
                if (PASSES == 2)
                    ldsm4(al[mi], rb + 16384 + co);
            }
#pragma unroll
            for (int j = 0; j < 2; j++) {
                uint32_t rb = st + BOFC + (uint32_t)((rowb + j * 16) * 128);
                ldsm4(bh[j], rb + (uint32_t)(((2 * ks + kb) ^ xb) * 16));
            }
#pragma unroll
            for (int mi = 0; mi < 4; mi++)
#pragma unroll
                for (int j = 0; j < 2; j++) {
                    mma16816(acc[mi][2 * j],     ah[mi], bh[j]);
                    mma16816(acc[mi][2 * j + 1], ah[mi], bh[j] + 2);
                }
            if (PASSES == 2) {
#pragma unroll
                for (int mi = 0; mi < 4; mi++)
#pragma unroll
                    for (int j = 0; j < 2; j++) {
                        mma16816(acc[mi][2 * j],     al[mi], bh[j]);
                        mma16816(acc[mi][2 * j + 1], al[mi], bh[j] + 2);
                    }
            }
        }
    };

#pragma unroll
    for (int i = 0; i < NST - 1; i++)
        if (i < KT) load(i, i);

    for (int ci = 0; ci < KT; ci++) {
        if (ci < KT - (NST - 1)) cp_wait<NST - 2>(); else cp_wait<0>();
        __syncthreads();
        if (ci + NST - 1 < KT) load(ci + NST - 1, (ci + NST - 1) % NST);
        compute(ci % NST);
    }

    const int rbase = m0 + wm * 64 + (lane >> 2);
    const int cbase = n0 + wn * 32 + (lane & 3) * 2;
#pragma unroll
    for (int mi = 0; mi < 4; mi++) {
#pragma unroll
        for (int ni = 0; ni < 4; ni++) {
#pragma unroll
            for (int h = 0; h < 2; h++) {
                int r = rbase + mi * 16 + h * 8;
                int c = cbase + ni * 8;
                float2 v;
                v.x = acc[mi][ni][2 * h]     * scale;
                v.y = acc[mi][ni][2 * h + 1] * scale;
                size_t go = (size_t)r * Nglob + c;
                if (Rp) {
                    float2 d = *(const float2*)(Rp + go);
                    v.x += d.x; v.y += d.y;
                }
                *(float2*)(Co + go) = v;
            }
        }
    }
}

// Merged scores + v_scores (both 2-pass, K=CDIM). grid = (128, 1, 2*NB).
__global__ void __launch_bounds__(256, 2)
gemm_dual(const hf* __restrict__ Xh, const hf* __restrict__ Xl,
          const hf* __restrict__ Kh, const hf* __restrict__ Vh,
          const hf* __restrict__ Vl, float* __restrict__ sc,
          float* __restrict__ vsc, float scale)
{
    extern __shared__ char dsm[];
    int which = blockIdx.z >= NB;
    int b = blockIdx.z & (NB - 1);
    if (!which) {
        int m0 = (blockIdx.x >> 2) * 128, n0 = (blockIdx.x & 3) * 128;
        gemm_body<2>(Xh + (size_t)b * TDIM * CDIM, Xl + (size_t)b * TDIM * CDIM,
                     Kh + (size_t)b * SDIM * CDIM, nullptr,
                     sc + (size_t)b * TDIM * SDIM, scale, CDIM, SDIM, m0, n0, dsm);
    } else {
        int m0 = (blockIdx.x >> 5) * 128, n0 = (blockIdx.x & 31) * 128;
        gemm_body<2>(Vh + (size_t)b * SDIM * CDIM, Vl + (size_t)b * SDIM * CDIM,
                     Xh + (size_t)b * TDIM * CDIM, nullptr,
                     vsc + (size_t)b * SDIM * TDIM, scale, CDIM, TDIM, m0, n0, dsm);
    }
}

// Merged k_t + v_t + att (all 1-pass). Long K=4096 tiles first.
__global__ void __launch_bounds__(256, 2)
gemm_tri(const hf* __restrict__ Ph, const hf* __restrict__ P2h,
         const hf* __restrict__ P3h, const hf* __restrict__ VTh,
         const hf* __restrict__ XTh, const float* __restrict__ kin,
         const float* __restrict__ vin, float* __restrict__ att,
         float* __restrict__ ktv, float* __restrict__ vtv)
{
    extern __shared__ char dsm[];
    int g = blockIdx.x;
    if (g < 512) {
        int isv = g >= 256;
        int r = g & 255;
        int b = r >> 5, t = r & 31;
        int m0 = (t >> 3) * 128, n0 = (t & 7) * 128;
        const hf* A = (isv ? P3h : P2h) + (size_t)b * SDIM * TDIM;
        const float* R = (isv ? vin : kin) + (size_t)b * SDIM * CDIM;
        float* C = (isv ? vtv : ktv) + (size_t)b * SDIM * CDIM;
        gemm_body<1>(A, nullptr, XTh + (size_t)b * CDIM * TDIM, R, C,
                     1.0f, TDIM, CDIM, m0, n0, dsm);
    } else {
        int r = g - 512;
        int b = r >> 8, t = r & 255;
        int m0 = (t >> 3) * 128, n0 = (t & 7) * 128;
        gemm_body<1>(Ph + (size_t)b * TDIM * SDIM, nullptr,
                     VTh + (size_t)b * CDIM * SDIM, nullptr,
                     att + (size_t)b * TDIM * CDIM, 1.0f, SDIM, CDIM, m0, n0, dsm);
    }
}

// ---------------- conversion kernels ----------------
__global__ void stx_k(const float* __restrict__ in, hf* __restrict__ oh,
                      hf* __restrict__ ol, hf* __restrict__ ohT, int R, int Cc)
{
    __shared__ float t[32][33];
    int b = blockIdx.z;
    int c0 = blockIdx.x * 32, r0 = blockIdx.y * 32;
    const float* ip = in + (size_t)b * R * Cc;
    size_t nb = (size_t)b * R * Cc;
    int tx = threadIdx.x, ty = threadIdx.y;
#pragma unroll
    for (int i = 0; i < 4; i++) {
        int r = r0 + ty + i * 8;
        float v = ip[(size_t)r * Cc + c0 + tx];
        t[ty + i * 8][tx] = v;
        hf h, l;
        split1(v, h, l);
        oh[nb + (size_t)r * Cc + c0 + tx] = h;
        if (ol) ol[nb + (size_t)r * Cc + c0 + tx] = l;
    }
    __syncthreads();
#pragma unroll
    for (int i = 0; i < 4; i++) {
        int c = c0 + ty + i * 8;
        ohT[nb + (size_t)c * R + r0 + tx] = __float2half_rn(t[tx][ty + i * 8]);
    }
}

__global__ void splith_k(const float* __restrict__ in, hf* __restrict__ h, size_t n4)
{
    size_t i = (size_t)blockIdx.x * blockDim.x + threadIdx.x;
    if (i >= n4) return;
    float4 v = ((const float4*)in)[i];
    __half2* hp = (__half2*)h;
    hp[i * 2]     = __halves2half2(__float2half_rn(v.x), __float2half_rn(v.y));
    hp[i * 2 + 1] = __halves2half2(__float2half_rn(v.z), __float2half_rn(v.w));
}

// FUSED row softmax over 512 + per-8-row column partials (one sc read)
__global__ void softfuse512_k(const float* __restrict__ S, hf* __restrict__ oh,
                              float* __restrict__ rmg, float* __restrict__ rsg,
                              float* __restrict__ pm, float* __restrict__ ps)
{
    __shared__ float sv[SDIM * 9];
    int warp = threadIdx.x >> 5, lane = threadIdx.x & 31;
    int b = blockIdx.y, rb = blockIdx.x;
    size_t row = (size_t)b * TDIM + rb * 8 + warp;
    const float4* p4 = (const float4*)(S + row * SDIM);
    float4 v[4];
    float m = NEG_INF;
#pragma unroll
    for (int i = 0; i < 4; i++) {
        v[i] = p4[lane + i * 32];
        m = fmaxf(m, fmaxf(fmaxf(v[i].x, v[i].y), fmaxf(v[i].z, v[i].w)));
        int c0 = 4 * (lane + i * 32);
        sv[(c0 + 0) * 9 + warp] = v[i].x;
        sv[(c0 + 1) * 9 + warp] = v[i].y;
        sv[(c0 + 2) * 9 + warp] = v[i].z;
        sv[(c0 + 3) * 9 + warp] = v[i].w;
    }
#pragma unroll
    for (int o = 16; o > 0; o >>= 1) m = fmaxf(m, __shfl_xor_sync(0xffffffffu, m, o));
    float s = 0.f;
#pragma unroll
    for (int i = 0; i < 4; i++)
        s += __expf(v[i].x - m) + __expf(v[i].y - m) + __expf(v[i].z - m) + __expf(v[i].w - m);
#pragma unroll
    for (int o = 16; o > 0; o >>= 1) s += __shfl_xor_sync(0xffffffffu, s, o);
    if (!lane) { rmg[row] = m; rsg[row] = s; }
    float inv = __fdividef(1.0f, s);
    __half2* hp = (__half2*)(oh + row * SDIM);
#pragma unroll
    for (int i = 0; i < 4; i++) {
        int p = (lane + i * 32) * 2;
        hp[p]     = __halves2half2(__float2half_rn(__expf(v[i].x - m) * inv),
                                   __float2half_rn(__expf(v[i].y - m) * inv));
        hp[p + 1] = __halves2half2(__float2half_rn(__expf(v[i].z - m) * inv),
                                   __float2half_rn(__expf(v[i].w - m) * inv));
    }
    __syncthreads();
#pragma unroll
    for (int h = 0; h < 2; h++) {
        int sc_ = threadIdx.x + h * 256;
        float cmx = NEG_INF;
#pragma unroll
        for (int w = 0; w < 8; w++) cmx = fmaxf(cmx, sv[sc_ * 9 + w]);
        float csum = 0.f;
#pragma unroll
        for (int w = 0; w < 8; w++) csum += __expf(sv[sc_ * 9 + w] - cmx);
        size_t o = ((size_t)b * NRCH + rb) * SDIM + sc_;
        pm[o] = cmx; ps[o] = csum;
    }
}

__global__ void colcomb1_k(const float* __restrict__ pm, const float* __restrict__ ps,
                           float* __restrict__ pm2, float* __restrict__ ps2)
{
    int b = blockIdx.y, g = blockIdx.x, s = threadIdx.x;
    float m = NEG_INF, sum = 0.f;
    for (int c = 0; c < NRCH / NCHUNK; c++) {
        size_t idx = ((size_t)b * NRCH + g * (NRCH / NCHUNK) + c) * SDIM + s;
        float mm = pm[idx];
        float nm = fmaxf(m, mm);
        sum = sum * __expf(m - nm) + ps[idx] * __expf(mm - nm);
        m = nm;
    }
    pm2[(b * NCHUNK + g) * SDIM + s] = m;
    ps2[(b * NCHUNK + g) * SDIM + s] = sum;
}

__global__ void colcomb_k(const float* __restrict__ pm, const float* __restrict__ ps,
                          float* __restrict__ cm, float* __restrict__ cs)
{
    int b = blockIdx.x, s = threadIdx.x;
    float m = NEG_INF;
#pragma unroll
    for (int c = 0; c < NCHUNK; c++) m = fmaxf(m, pm[(b * NCHUNK + c) * SDIM + s]);
    float sum = 0.f;
#pragma unroll
    for (int c = 0; c < NCHUNK; c++)
        sum += ps[(b * NCHUNK + c) * SDIM + s] * __expf(pm[(b * NCHUNK + c) * SDIM + s] - m);
    cm[b * SDIM + s] = m;
    cs[b * SDIM + s] = sum;
}

// col softmax + transpose from Ph
__global__ void pcolT_k(const hf* __restrict__ Ph, const float* __restrict__ rmg,
                        const float* __restrict__ rsg, const float* __restrict__ cm,
                        const float* __restrict__ cs, hf* __restrict__ oh)
{
    __shared__ float t[32][33];
    int b = blockIdx.z;
    int s0 = blockIdx.x * 32, t0 = blockIdx.y * 32;
    const hf* ip = Ph + (size_t)b * TDIM * SDIM;
    int tx = threadIdx.x, ty = threadIdx.y;
#pragma unroll
    for (int i = 0; i < 4; i++) {
        int tr = t0 + ty + i * 8;
        t[ty + i * 8][tx] = __half2float(ip[(size_t)tr * SDIM + s0 + tx]);
    }
    __syncthreads();
    size_t ob = (size_t)b * SDIM * TDIM;
#pragma unroll
    for (int i = 0; i < 4; i++) {
        int s = s0 + ty + i * 8;
        int tcol = t0 + tx;
        float cminv = __fdividef(1.0f, cs[b * SDIM + s]);
        float cmv = cm[b * SDIM + s];
        float f = rsg[b * TDIM + tcol] * __expf(rmg[b * TDIM + tcol] - cmv) * cminv;
        oh[ob + (size_t)s * TDIM + t0 + tx] = __float2half_rn(t[tx][ty + i * 8] * f);
    }
}

// row softmax over 4096 -> fp16 hi only
__global__ void softrow4096_k(const float* __restrict__ S, hf* __restrict__ oh)
{
    __shared__ float sh[16];
    int tid = threadIdx.x, lane = tid & 31, warp = tid >> 5;
    size_t row = blockIdx.x;
    const float4* p4 = (const float4*)(S + row * TDIM);
    float4 v[2];
    float m = NEG_INF;
#pragma unroll
    for (int i = 0; i < 2; i++) {
        v[i] = p4[tid + i * 512];
        m = fmaxf(m, fmaxf(fmaxf(v[i].x, v[i].y), fmaxf(v[i].z, v[i].w)));
    }
#pragma unroll
    for (int o = 16; o > 0; o >>= 1) m = fmaxf(m, __shfl_xor_sync(0xffffffffu, m, o));
    if (!lane) sh[warp] = m;
    __syncthreads();
    if (tid < 16) {
        float t = sh[tid];
#pragma unroll
        for (int o = 8; o > 0; o >>= 1) t = fmaxf(t, __shfl_xor_sync(0xffffu, t, o));
        if (!tid) sh[0] = t;
    }
    __syncthreads();
    m = sh[0];
    __syncthreads();
    float s = 0.f;
#pragma unroll
    for (int i = 0; i < 2; i++)
        s += __expf(v[i].x - m) + __expf(v[i].y - m) + __expf(v[i].z - m) + __expf(v[i].w - m);
#pragma unroll
    for (int o = 16; o > 0; o >>= 1) s += __shfl_xor_sync(0xffffffffu, s, o);
    if (!lane) sh[warp] = s;
    __syncthreads();
    if (tid < 16) {
        float t = sh[tid];
#pragma unroll
        for (int o = 8; o > 0; o >>= 1) t += __shfl_xor_sync(0xffffu, t, o);
        if (!tid) sh[0] = t;
    }
    __syncthreads();
    float inv = __fdividef(1.0f, sh[0]);
    __half2* hp = (__half2*)(oh + row * TDIM);
#pragma unroll
    for (int i = 0; i < 2; i++) {
        int p = (tid + i * 512) * 2;
        hp[p]     = __halves2half2(__float2half_rn(__expf(v[i].x - m) * inv),
                                   __float2half_rn(__expf(v[i].y - m) * inv));
        hp[p + 1] = __halves2half2(__float2half_rn(__expf(v[i].z - m) * inv),
                                   __float2half_rn(__expf(v[i].w - m) * inv));
    }
}

// ---------------- launch ----------------
extern "C" void kernel_launch(void* const* d_in, const int* in_sizes, int n_in,
                              void* d_out, int out_size)
{
    const float* x   = (const float*)d_in[0];
    const float* kin = (const float*)d_in[1];
    const float* vin = (const float*)d_in[2];

    float* att = (float*)d_out;
    float* ktv = att + (size_t)NB * TDIM * CDIM;
    float* vtv = ktv + (size_t)NB * SDIM * CDIM;

    float *sc, *vsc, *pmL, *psL, *pcm, *pcs, *cm, *cs, *rm, *rs;
    hf *Xh, *Xl, *XTh, *Kh, *Vh, *Vl, *VTh;
    hf *Ph, *P2h, *P3h;
    cudaGetSymbolAddress((void**)&sc, g_sc);     cudaGetSymbolAddress((void**)&vsc, g_vsc);
    cudaGetSymbolAddress((void**)&pmL, g_pmL);   cudaGetSymbolAddress((void**)&psL, g_psL);
    cudaGetSymbolAddress((void**)&pcm, g_pcm);   cudaGetSymbolAddress((void**)&pcs, g_pcs);
    cudaGetSymbolAddress((void**)&cm, g_cm);     cudaGetSymbolAddress((void**)&cs, g_cs);
    cudaGetSymbolAddress((void**)&rm, g_rm);     cudaGetSymbolAddress((void**)&rs, g_rs);
    cudaGetSymbolAddress((void**)&Xh, g_Xh);     cudaGetSymbolAddress((void**)&Xl, g_Xl);
    cudaGetSymbolAddress((void**)&XTh, g_XTh);
    cudaGetSymbolAddress((void**)&Kh, g_Kh);
    cudaGetSymbolAddress((void**)&Vh, g_Vh);     cudaGetSymbolAddress((void**)&Vl, g_Vl);
    cudaGetSymbolAddress((void**)&VTh, g_VTh);
    cudaGetSymbolAddress((void**)&Ph, g_Ph);
    cudaGetSymbolAddress((void**)&P2h, g_P2h);
    cudaGetSymbolAddress((void**)&P3h, g_P3h);

    const int SMEM = 98304;
    cudaFuncSetAttribute(gemm_dual, cudaFuncAttributeMaxDynamicSharedMemorySize, SMEM);
    cudaFuncSetAttribute(gemm_tri,  cudaFuncAttributeMaxDynamicSharedMemorySize, SMEM);

    const float scale = 0.03125f;  // 1/sqrt(1024)

    // operand prep
    stx_k<<<dim3(CDIM / 32, TDIM / 32, NB), dim3(32, 8)>>>(x, Xh, Xl, XTh, TDIM, CDIM);
    {
        size_t n4 = (size_t)NB * SDIM * CDIM / 4;
        splith_k<<<(unsigned)((n4 + 255) / 256), 256>>>(kin, Kh, n4);
    }
    stx_k<<<dim3(CDIM / 32, SDIM / 32, NB), dim3(32, 8)>>>(vin, Vh, Vl, VTh, SDIM, CDIM);

    // merged scores + v_scores (2-pass, K=1024), 2048 CTAs
    gemm_dual<<<dim3(128, 1, 2 * NB), 256, SMEM>>>(Xh, Xl, Kh, Vh, Vl, sc, vsc, scale);

    // aux chain
    softfuse512_k<<<dim3(NRCH, NB), 256>>>(sc, Ph, rm, rs, pmL, psL);
    colcomb1_k<<<dim3(NCHUNK, NB), SDIM>>>(pmL, psL, pcm, pcs);
    colcomb_k<<<NB, SDIM>>>(pcm, pcs, cm, cs);
    pcolT_k<<<dim3(SDIM / 32, TDIM / 32, NB), dim3(32, 8)>>>(Ph, rm, rs, cm, cs, P2h);
    softrow4096_k<<<NB * SDIM, 512>>>(vsc, P3h);

    // merged k_t + v_t + att (1-pass), long tiles first, 2560 CTAs
    gemm_tri<<<2560, 256, SMEM>>>(Ph, P2h, P3h, VTh, XTh, kin, vin, att, ktv, vtv);
}

// round 17
// speedup vs baseline: 1.5400x; 1.0154x over previous
#include <cuda_runtime.h>
#include <cuda_fp16.h>
#include <cstdint>

#define NB 8
#define TDIM 4096
#define SDIM 512
#define CDIM 1024
#define NCHUNK 16
#define NRCH 512
#define NEG_INF (-3.0e38f)

typedef __half hf;

// ---------------- scratch (static device globals; no allocation) ----------------
__device__ float g_sc [(size_t)NB * TDIM * SDIM];
__device__ float g_vsc[(size_t)NB * SDIM * TDIM];
__device__ __align__(16) hf g_Xh [(size_t)NB * TDIM * CDIM], g_Xl [(size_t)NB * TDIM * CDIM];
__device__ __align__(16) hf g_XTh[(size_t)NB * CDIM * TDIM];
__device__ __align__(16) hf g_Kh [(size_t)NB * SDIM * CDIM];
__device__ __align__(16) hf g_Vh [(size_t)NB * SDIM * CDIM], g_Vl [(size_t)NB * SDIM * CDIM];
__device__ __align__(16) hf g_VTh[(size_t)NB * CDIM * SDIM];
__device__ __align__(16) hf g_Ph [(size_t)NB * TDIM * SDIM];
__device__ __align__(16) hf g_P2h[(size_t)NB * SDIM * TDIM];
__device__ __align__(16) hf g_P3h[(size_t)NB * SDIM * TDIM];
__device__ float g_pmL[(size_t)NB * NRCH * SDIM], g_psL[(size_t)NB * NRCH * SDIM];
__device__ float g_pcm[NB * NCHUNK * SDIM], g_pcs[NB * NCHUNK * SDIM];
__device__ float g_cm [NB * SDIM], g_cs [NB * SDIM];
__device__ float g_rm [NB * TDIM], g_rs [NB * TDIM];

// ---------------- PTX helpers ----------------
__device__ __forceinline__ void cp16(uint32_t dst, const void* src) {
    asm volatile("cp.async.cg.shared.global [%0], [%1], 16;" :: "r"(dst), "l"(src));
}
__device__ __forceinline__ void cp_commit() {
    asm volatile("cp.async.commit_group;" ::: "memory");
}
template <int N>
__device__ __forceinline__ void cp_wait() {
    asm volatile("cp.async.wait_group %0;" :: "n"(N) : "memory");
}
__device__ __forceinline__ void ldsm4(uint32_t* r, uint32_t addr) {
    asm volatile("ldmatrix.sync.aligned.m8n8.x4.shared.b16 {%0,%1,%2,%3}, [%4];"
                 : "=r"(r[0]), "=r"(r[1]), "=r"(r[2]), "=r"(r[3]) : "r"(addr));
}
__device__ __forceinline__ void mma16816(float* d, const uint32_t* a, const uint32_t* b) {
    asm volatile(
        "mma.sync.aligned.m16n8k16.row.col.f32.f16.f16.f32 "
        "{%0,%1,%2,%3}, {%4,%5,%6,%7}, {%8,%9}, {%0,%1,%2,%3};"
        : "+f"(d[0]), "+f"(d[1]), "+f"(d[2]), "+f"(d[3])
        : "r"(a[0]), "r"(a[1]), "r"(a[2]), "r"(a[3]), "r"(b[0]), "r"(b[1]));
}
__device__ __forceinline__ void split1(float f, hf& h, hf& l) {
    h = __float2half_rn(f);
    l = __float2half_rn(f - __half2float(h));
}

// ---------------------------------------------------------------------------
// Shared GEMM body (unchanged from R15/R16).
// ---------------------------------------------------------------------------
template <int PASSES>
__device__ __forceinline__ void gemm_body(
    const hf* __restrict__ pAh, const hf* __restrict__ pAl,
    const hf* __restrict__ pBh, const float* __restrict__ Rp,
    float* __restrict__ Co, float scale, int K, int Nglob,
    int m0, int n0, char* dsm)
{
    constexpr int NST  = (PASSES == 1) ? 3 : 2;
    constexpr int STG  = (PASSES == 1) ? 32768 : 49152;
    constexpr int BOFC = (PASSES == 1) ? 16384 : 32768;
    constexpr int NCH  = (PASSES == 1) ? 8 : 12;

    const uint32_t sbase = (uint32_t)__cvta_generic_to_shared(dsm);
    const int tid = threadIdx.x, wid = tid >> 5, lane = tid & 31;
    const int wm = wid & 1, wn = wid >> 1;
    const int KT = K >> 6;

    auto load = [&](int kc, int s) {
        uint32_t st = sbase + s * STG;
#pragma unroll
        for (int t = 0; t < NCH; t++) {
            int idx = t * 256 + tid;
            int tile = idx >> 10;
            int ch = idx & 1023;
            int row = ch >> 3, c = ch & 7;
            const hf* src;
            int rbase;
            if (PASSES == 2) {
                src = (tile == 0) ? pAh : (tile == 1 ? pAl : pBh);
                rbase = (tile < 2) ? m0 : n0;
            } else {
                src = (tile == 0) ? pAh : pBh;
                rbase = (tile == 0) ? m0 : n0;
            }
            size_t goff = (size_t)(rbase + row) * K + kc * 64 + c * 8;
            uint32_t dst = st + (uint32_t)(tile * 16384 + row * 128 + ((c ^ (row & 7)) * 16));
            cp16(dst, (const char*)src + goff * 2);
        }
        cp_commit();
    };

    float acc[4][4][4];
#pragma unroll
    for (int mi = 0; mi < 4; mi++)
#pragma unroll
        for (int ni = 0; ni < 4; ni++)
#pragma unroll
            for (int j = 0; j < 4; j++) acc[mi][ni][j] = 0.f;

    const int rowa = wm * 64 + (lane & 15);
    const int ka   = lane >> 4;
    const int xa   = rowa & 7;
    const int rowb = wn * 32 + (lane & 7) + ((lane >> 4) << 3);
    const int kb   = (lane >> 3) & 1;
    const int xb   = rowb & 7;

    auto compute = [&](int s) {
        uint32_t st = sbase + s * STG;
#pragma unroll
        for (int ks = 0; ks < 4; ks++) {
            uint32_t ah[4][4], al[4][4], bh[2][4];
#pragma unroll
            for (int mi = 0; mi < 4; mi++) {
                uint32_t rb = st + (uint32_t)((rowa + mi * 16) * 128);
                uint32_t co = (uint32_t)(((2 * ks + ka) ^ xa) * 16);
                ldsm4(ah[mi], rb + co);
                if (PASSES == 2)
                    ldsm4(al[mi], rb + 16384 + co);
            }
#pragma unroll
            for (int j = 0; j < 2; j++) {
                uint32_t rb = st + BOFC + (uint32_t)((rowb + j * 16) * 128);
                ldsm4(bh[j], rb + (uint32_t)(((2 * ks + kb) ^ xb) * 16));
            }
#pragma unroll
            for (int mi = 0; mi < 4; mi++)
#pragma unroll
                for (int j = 0; j < 2; j++) {
                    mma16816(acc[mi][2 * j],     ah[mi], bh[j]);
                    mma16816(acc[mi][2 * j + 1], ah[mi], bh[j] + 2);
                }
            if (PASSES == 2) {
#pragma unroll
                for (int mi = 0; mi < 4; mi++)
#pragma unroll
                    for (int j = 0; j < 2; j++) {
                        mma16816(acc[mi][2 * j],     al[mi], bh[j]);
                        mma16816(acc[mi][2 * j + 1], al[mi], bh[j] + 2);
                    }
            }
        }
    };

#pragma unroll
    for (int i = 0; i < NST - 1; i++)
        if (i < KT) load(i, i);

    for (int ci = 0; ci < KT; ci++) {
        if (ci < KT - (NST - 1)) cp_wait<NST - 2>(); else cp_wait<0>();
        __syncthreads();
        if (ci + NST - 1 < KT) load(ci + NST - 1, (ci + NST - 1) % NST);
        compute(ci % NST);
    }

    const int rbase = m0 + wm * 64 + (lane >> 2);
    const int cbase = n0 + wn * 32 + (lane & 3) * 2;
#pragma unroll
    for (int mi = 0; mi < 4; mi++) {
#pragma unroll
        for (int ni = 0; ni < 4; ni++) {
#pragma unroll
            for (int h = 0; h < 2; h++) {
                int r = rbase + mi * 16 + h * 8;
                int c = cbase + ni * 8;
                float2 v;
                v.x = acc[mi][ni][2 * h]     * scale;
                v.y = acc[mi][ni][2 * h + 1] * scale;
                size_t go = (size_t)r * Nglob + c;
                if (Rp) {
                    float2 d = *(const float2*)(Rp + go);
                    v.x += d.x; v.y += d.y;
                }
                *(float2*)(Co + go) = v;
            }
        }
    }
}

// Merged scores + v_scores
__global__ void __launch_bounds__(256, 2)
gemm_dual(const hf* __restrict__ Xh, const hf* __restrict__ Xl,
          const hf* __restrict__ Kh, const hf* __restrict__ Vh,
          const hf* __restrict__ Vl, float* __restrict__ sc,
          float* __restrict__ vsc, float scale)
{
    extern __shared__ char dsm[];
    int which = blockIdx.z >= NB;
    int b = blockIdx.z & (NB - 1);
    if (!which) {
        int m0 = (blockIdx.x >> 2) * 128, n0 = (blockIdx.x & 3) * 128;
        gemm_body<2>(Xh + (size_t)b * TDIM * CDIM, Xl + (size_t)b * TDIM * CDIM,
                     Kh + (size_t)b * SDIM * CDIM, nullptr,
                     sc + (size_t)b * TDIM * SDIM, scale, CDIM, SDIM, m0, n0, dsm);
    } else {
        int m0 = (blockIdx.x >> 5) * 128, n0 = (blockIdx.x & 31) * 128;
        gemm_body<2>(Vh + (size_t)b * SDIM * CDIM, Vl + (size_t)b * SDIM * CDIM,
                     Xh + (size_t)b * TDIM * CDIM, nullptr,
                     vsc + (size_t)b * SDIM * TDIM, scale, CDIM, TDIM, m0, n0, dsm);
    }
}

// Merged k_t + v_t + att
__global__ void __launch_bounds__(256, 2)
gemm_tri(const hf* __restrict__ Ph, const hf* __restrict__ P2h,
         const hf* __restrict__ P3h, const hf* __restrict__ VTh,
         const hf* __restrict__ XTh, const float* __restrict__ kin,
         const float* __restrict__ vin, float* __restrict__ att,
         float* __restrict__ ktv, float* __restrict__ vtv)
{
    extern __shared__ char dsm[];
    int g = blockIdx.x;
    if (g < 512) {
        int isv = g >= 256;
        int r = g & 255;
        int b = r >> 5, t = r & 31;
        int m0 = (t >> 3) * 128, n0 = (t & 7) * 128;
        const hf* A = (isv ? P3h : P2h) + (size_t)b * SDIM * TDIM;
        const float* R = (isv ? vin : kin) + (size_t)b * SDIM * CDIM;
        float* C = (isv ? vtv : ktv) + (size_t)b * SDIM * CDIM;
        gemm_body<1>(A, nullptr, XTh + (size_t)b * CDIM * TDIM, R, C,
                     1.0f, TDIM, CDIM, m0, n0, dsm);
    } else {
        int r = g - 512;
        int b = r >> 8, t = r & 255;
        int m0 = (t >> 3) * 128, n0 = (t & 7) * 128;
        gemm_body<1>(Ph + (size_t)b * TDIM * SDIM, nullptr,
                     VTh + (size_t)b * CDIM * SDIM, nullptr,
                     att + (size_t)b * TDIM * CDIM, 1.0f, SDIM, CDIM, m0, n0, dsm);
    }
}

// ---------------------------------------------------------------------------
// MERGED prep: X split(hi,lo)+transpose | V split(hi,lo)+transpose | K hi-only
// grid.x = 32768 (X) + 4096 (V) + 4096 (K) = 40960, 256 threads.
// ---------------------------------------------------------------------------
__device__ __forceinline__ void stx_body(const float* __restrict__ ip, hf* oh,
                                         hf* ol, hf* ohT, size_t nb, int R, int Cc,
                                         int c0, int r0, float (*t)[33])
{
    int tx = threadIdx.x & 31, ty = threadIdx.x >> 5;
#pragma unroll
    for (int i = 0; i < 4; i++) {
        int r = r0 + ty + i * 8;
        float v = ip[(size_t)r * Cc + c0 + tx];
        t[ty + i * 8][tx] = v;
        hf h, l;
        split1(v, h, l);
        oh[nb + (size_t)r * Cc + c0 + tx] = h;
        ol[nb + (size_t)r * Cc + c0 + tx] = l;
    }
    __syncthreads();
#pragma unroll
    for (int i = 0; i < 4; i++) {
        int c = c0 + ty + i * 8;
        ohT[nb + (size_t)c * R + r0 + tx] = __float2half_rn(t[tx][ty + i * 8]);
    }
}

__global__ void prep_k(const float* __restrict__ x, const float* __restrict__ kin,
                       const float* __restrict__ vin,
                       hf* __restrict__ Xh, hf* __restrict__ Xl, hf* __restrict__ XTh,
                       hf* __restrict__ Kh, hf* __restrict__ Vh, hf* __restrict__ Vl,
                       hf* __restrict__ VTh)
{
    __shared__ float t[32][33];
    int g = blockIdx.x;
    if (g < 32768) {                       // X: 32 cblk x 128 rblk x 8 batches
        int b = g >> 12, rem = g & 4095;
        int c0 = (rem & 31) * 32, r0 = (rem >> 5) * 32;
        stx_body(x + (size_t)b * TDIM * CDIM, Xh, Xl, XTh,
                 (size_t)b * TDIM * CDIM, TDIM, CDIM, c0, r0, t);
    } else if (g < 36864) {                // V: 32 cblk x 16 rblk x 8 batches
        int r2 = g - 32768;
        int b = r2 >> 9, rem = r2 & 511;
        int c0 = (rem & 31) * 32, r0 = (rem >> 5) * 32;
        stx_body(vin + (size_t)b * SDIM * CDIM, Vh, Vl, VTh,
                 (size_t)b * SDIM * CDIM, SDIM, CDIM, c0, r0, t);
    } else {                               // K hi-only: 4096 blocks x 256 thr
        size_t i = (size_t)(g - 36864) * 256 + threadIdx.x;  // < NB*SDIM*CDIM/4
        float4 v = ((const float4*)kin)[i];
        __half2* hp = (__half2*)Kh;
        hp[i * 2]     = __halves2half2(__float2half_rn(v.x), __float2half_rn(v.y));
        hp[i * 2 + 1] = __halves2half2(__float2half_rn(v.z), __float2half_rn(v.w));
    }
}

// ---------------------------------------------------------------------------
// MERGED softmax: softfuse512 (sc -> Ph,rm,rs,pmL,psL) | softrow4096 (vsc -> P3h)
// grid.x = 4096 + 4096, 256 threads, 18 KB smem (softfuse branch).
// ---------------------------------------------------------------------------
__global__ void softall_k(const float* __restrict__ S, const float* __restrict__ VS,
                          hf* __restrict__ oh, hf* __restrict__ oh3,
                          float* __restrict__ rmg, float* __restrict__ rsg,
                          float* __restrict__ pm, float* __restrict__ ps)
{
    __shared__ float sv[SDIM * 9];         // 18 KB
    int g = blockIdx.x;
    if (g < 4096) {
        // ---- softfuse512 ----
        int warp = threadIdx.x >> 5, lane = threadIdx.x & 31;
        int b = g >> 9, rb = g & 511;
        size_t row = (size_t)b * TDIM + rb * 8 + warp;
        const float4* p4 = (const float4*)(S + row * SDIM);
        float4 v[4];
        float m = NEG_INF;
#pragma unroll
        for (int i = 0; i < 4; i++) {
            v[i] = p4[lane + i * 32];
            m = fmaxf(m, fmaxf(fmaxf(v[i].x, v[i].y), fmaxf(v[i].z, v[i].w)));
            int c0 = 4 * (lane + i * 32);
            sv[(c0 + 0) * 9 + warp] = v[i].x;
            sv[(c0 + 1) * 9 + warp] = v[i].y;
            sv[(c0 + 2) * 9 + warp] = v[i].z;
            sv[(c0 + 3) * 9 + warp] = v[i].w;
        }
#pragma unroll
        for (int o = 16; o > 0; o >>= 1) m = fmaxf(m, __shfl_xor_sync(0xffffffffu, m, o));
        float s = 0.f;
#pragma unroll
        for (int i = 0; i < 4; i++)
            s += __expf(v[i].x - m) + __expf(v[i].y - m) + __expf(v[i].z - m) + __expf(v[i].w - m);
#pragma unroll
        for (int o = 16; o > 0; o >>= 1) s += __shfl_xor_sync(0xffffffffu, s, o);
        if (!lane) { rmg[row] = m; rsg[row] = s; }
        float inv = __fdividef(1.0f, s);
        __half2* hp = (__half2*)(oh + row * SDIM);
#pragma unroll
        for (int i = 0; i < 4; i++) {
            int p = (lane + i * 32) * 2;
            hp[p]     = __halves2half2(__float2half_rn(__expf(v[i].x - m) * inv),
                                       __float2half_rn(__expf(v[i].y - m) * inv));
            hp[p + 1] = __halves2half2(__float2half_rn(__expf(v[i].z - m) * inv),
                                       __float2half_rn(__expf(v[i].w - m) * inv));
        }
        __syncthreads();
#pragma unroll
        for (int h = 0; h < 2; h++) {
            int sc_ = threadIdx.x + h * 256;
            float cmx = NEG_INF;
#pragma unroll
            for (int w = 0; w < 8; w++) cmx = fmaxf(cmx, sv[sc_ * 9 + w]);
            float csum = 0.f;
#pragma unroll
            for (int w = 0; w < 8; w++) csum += __expf(sv[sc_ * 9 + w] - cmx);
            size_t o = ((size_t)b * NRCH + rb) * SDIM + sc_;
            pm[o] = cmx; ps[o] = csum;
        }
    } else {
        // ---- softrow4096 (256 thr, 4 float4/thread) ----
        int tid = threadIdx.x, lane = tid & 31, warp = tid >> 5;
        size_t row = (size_t)(g - 4096);
        const float4* p4 = (const float4*)(VS + row * TDIM);
        float4 v[4];
        float m = NEG_INF;
#pragma unroll
        for (int i = 0; i < 4; i++) {
            v[i] = p4[tid + i * 256];
            m = fmaxf(m, fmaxf(fmaxf(v[i].x, v[i].y), fmaxf(v[i].z, v[i].w)));
        }
#pragma unroll
        for (int o = 16; o > 0; o >>= 1) m = fmaxf(m, __shfl_xor_sync(0xffffffffu, m, o));
        if (!lane) sv[warp] = m;
        __syncthreads();
        if (tid < 8) {
            float t = sv[tid];
#pragma unroll
            for (int o = 4; o > 0; o >>= 1) t = fmaxf(t, __shfl_xor_sync(0xffu, t, o));
            if (!tid) sv[0] = t;
        }
        __syncthreads();
        m = sv[0];
        __syncthreads();
        float s = 0.f;
#pragma unroll
        for (int i = 0; i < 4; i++)
            s += __expf(v[i].x - m) + __expf(v[i].y - m) + __expf(v[i].z - m) + __expf(v[i].w - m);
#pragma unroll
        for (int o = 16; o > 0; o >>= 1) s += __shfl_xor_sync(0xffffffffu, s, o);
        if (!lane) sv[warp] = s;
        __syncthreads();
        if (tid < 8) {
            float t = sv[tid];
#pragma unroll
            for (int o = 4; o > 0; o >>= 1) t += __shfl_xor_sync(0xffu, t, o);
            if (!tid) sv[0] = t;
        }
        __syncthreads();
        float inv = __fdividef(1.0f, sv[0]);
        __half2* hp = (__half2*)(oh3 + row * TDIM);
#pragma unroll
        for (int i = 0; i < 4; i++) {
            int p = (tid + i * 256) * 2;
            hp[p]     = __halves2half2(__float2half_rn(__expf(v[i].x - m) * inv),
                                       __float2half_rn(__expf(v[i].y - m) * inv));
            hp[p + 1] = __halves2half2(__float2half_rn(__expf(v[i].z - m) * inv),
                                       __float2half_rn(__expf(v[i].w - m) * inv));
        }
    }
}

// ---------------- column-softmax combine + pcolT (unchanged) ----------------
__global__ void colcomb1_k(const float* __restrict__ pm, const float* __restrict__ ps,
                           float* __restrict__ pm2, float* __restrict__ ps2)
{
    int b = blockIdx.y, g = blockIdx.x, s = threadIdx.x;
    float m = NEG_INF, sum = 0.f;
    for (int c = 0; c < NRCH / NCHUNK; c++) {
        size_t idx = ((size_t)b * NRCH + g * (NRCH / NCHUNK) + c) * SDIM + s;
        float mm = pm[idx];
        float nm = fmaxf(m, mm);
        sum = sum * __expf(m - nm) + ps[idx] * __expf(mm - nm);
        m = nm;
    }
    pm2[(b * NCHUNK + g) * SDIM + s] = m;
    ps2[(b * NCHUNK + g) * SDIM + s] = sum;
}

__global__ void colcomb_k(const float* __restrict__ pm, const float* __restrict__ ps,
                          float* __restrict__ cm, float* __restrict__ cs)
{
    int b = blockIdx.x, s = threadIdx.x;
    float m = NEG_INF;
#pragma unroll
    for (int c = 0; c < NCHUNK; c++) m = fmaxf(m, pm[(b * NCHUNK + c) * SDIM + s]);
    float sum = 0.f;
#pragma unroll
    for (int c = 0; c < NCHUNK; c++)
        sum += ps[(b * NCHUNK + c) * SDIM + s] * __expf(pm[(b * NCHUNK + c) * SDIM + s] - m);
    cm[b * SDIM + s] = m;
    cs[b * SDIM + s] = sum;
}

__global__ void pcolT_k(const hf* __restrict__ Ph, const float* __restrict__ rmg,
                        const float* __restrict__ rsg, const float* __restrict__ cm,
                        const float* __restrict__ cs, hf* __restrict__ oh)
{
    __shared__ float t[32][33];
    int b = blockIdx.z;
    int s0 = blockIdx.x * 32, t0 = blockIdx.y * 32;
    const hf* ip = Ph + (size_t)b * TDIM * SDIM;
    int tx = threadIdx.x, ty = threadIdx.y;
#pragma unroll
    for (int i = 0; i < 4; i++) {
        int tr = t0 + ty + i * 8;
        t[ty + i * 8][tx] = __half2float(ip[(size_t)tr * SDIM + s0 + tx]);
    }
    __syncthreads();
    size_t ob = (size_t)b * SDIM * TDIM;
#pragma unroll
    for (int i = 0; i < 4; i++) {
        int s = s0 + ty + i * 8;
        int tcol = t0 + tx;
        float cminv = __fdividef(1.0f, cs[b * SDIM + s]);
        float cmv = cm[b * SDIM + s];
        float f = rsg[b * TDIM + tcol] * __expf(rmg[b * TDIM + tcol] - cmv) * cminv;
        oh[ob + (size_t)s * TDIM + t0 + tx] = __float2half_rn(t[tx][ty + i * 8] * f);
    }
}

// ---------------- launch ----------------
extern "C" void kernel_launch(void* const* d_in, const int* in_sizes, int n_in,
                              void* d_out, int out_size)
{
    const float* x   = (const float*)d_in[0];
    const float* kin = (const float*)d_in[1];
    const float* vin = (const float*)d_in[2];

    float* att = (float*)d_out;
    float* ktv = att + (size_t)NB * TDIM * CDIM;
    float* vtv = ktv + (size_t)NB * SDIM * CDIM;

    float *sc, *vsc, *pmL, *psL, *pcm, *pcs, *cm, *cs, *rm, *rs;
    hf *Xh, *Xl, *XTh, *Kh, *Vh, *Vl, *VTh;
    hf *Ph, *P2h, *P3h;
    cudaGetSymbolAddress((void**)&sc, g_sc);     cudaGetSymbolAddress((void**)&vsc, g_vsc);
    cudaGetSymbolAddress((void**)&pmL, g_pmL);   cudaGetSymbolAddress((void**)&psL, g_psL);
    cudaGetSymbolAddress((void**)&pcm, g_pcm);   cudaGetSymbolAddress((void**)&pcs, g_pcs);
    cudaGetSymbolAddress((void**)&cm, g_cm);     cudaGetSymbolAddress((void**)&cs, g_cs);
    cudaGetSymbolAddress((void**)&rm, g_rm);     cudaGetSymbolAddress((void**)&rs, g_rs);
    cudaGetSymbolAddress((void**)&Xh, g_Xh);     cudaGetSymbolAddress((void**)&Xl, g_Xl);
    cudaGetSymbolAddress((void**)&XTh, g_XTh);
    cudaGetSymbolAddress((void**)&Kh, g_Kh);
    cudaGetSymbolAddress((void**)&Vh, g_Vh);     cudaGetSymbolAddress((void**)&Vl, g_Vl);
    cudaGetSymbolAddress((void**)&VTh, g_VTh);
    cudaGetSymbolAddress((void**)&Ph, g_Ph);
    cudaGetSymbolAddress((void**)&P2h, g_P2h);
    cudaGetSymbolAddress((void**)&P3h, g_P3h);

    const int SMEM = 98304;
    cudaFuncSetAttribute(gemm_dual, cudaFuncAttributeMaxDynamicSharedMemorySize, SMEM);
    cudaFuncSetAttribute(gemm_tri,  cudaFuncAttributeMaxDynamicSharedMemorySize, SMEM);

    const float scale = 0.03125f;  // 1/sqrt(1024)

    // merged operand prep (X | V | K), 40960 CTAs
    prep_k<<<40960, 256>>>(x, kin, vin, Xh, Xl, XTh, Kh, Vh, Vl, VTh);

    // merged scores + v_scores (2-pass, K=1024), 2048 CTAs
    gemm_dual<<<dim3(128, 1, 2 * NB), 256, SMEM>>>(Xh, Xl, Kh, Vh, Vl, sc, vsc, scale);

    // merged softmax (softfuse512 | softrow4096), 8192 CTAs
    softall_k<<<8192, 256>>>(sc, vsc, Ph, P3h, rm, rs, pmL, psL);
    colcomb1_k<<<dim3(NCHUNK, NB), SDIM>>>(pmL, psL, pcm, pcs);
    colcomb_k<<<NB, SDIM>>>(pcm, pcs, cm, cs);
    pcolT_k<<<dim3(SDIM / 32, TDIM / 32, NB), dim3(32, 8)>>>(Ph, rm, rs, cm, cs, P2h);

    // merged k_t + v_t + att (1-pass), long tiles first, 2560 CTAs
    gemm_tri<<<2560, 256, SMEM>>>(Ph, P2h, P3h, VTh, XTh, kin, vin, att, ktv, vtv);
}